// round 10
// baseline (speedup 1.0000x reference)
#include <cuda_runtime.h>

// IoU3DLoss: per-pair rotated 3D IoU -> mean((1-iou)*weight)
// Round 10 = round-9 math (abs-form slab clips, corner-cross algebra, fast divide,
// fence-free packed-u64 deterministic reduction) plus:
//  - __launch_bounds__(128, 14): regs 40 -> 36, 12 -> 14 blocks/SM (87.5% theo occ)
//  - __ldcs streaming loads (read-once data, evict-first; keep L2 clean)
//  - minor CSE in B-corner construction

constexpr int BLOCK = 128;
constexpr double FP_SCALE = 8388608.0;            // 2^23
constexpr unsigned long long SUM_MASK = (1ull << 44) - 1ull;
constexpr unsigned long long CNT_ONE  = 1ull << 44;

__device__ unsigned long long g_acc = 0ull;       // reset by last block each launch

// t-interval length inside both slabs, intersected with [0,1].
// pu = u0*idu, qu = |W*idu| (axis-u), likewise v. lo = -p-q, hi = q-p.
__device__ __forceinline__ float clip_core(float pu, float qu, float pv, float qv)
{
    float lo1 = -pu - qu, hi1 = qu - pu;
    float lo2 = -pv - qv, hi2 = qv - pv;
    float tmin = fmaxf(fmaxf(lo1, lo2), 0.0f);
    float tmax = fminf(fminf(hi1, hi2), 1.0f);
    return fmaxf(tmax - tmin, 0.0f);
}

__device__ __forceinline__ float pair_loss(
    float x1, float y1, float z1, float w1, float h1, float d1, float a1,
    float x2, float y2, float z2, float w2, float h2, float d2, float a2,
    float wgt)
{
    // B(target) local frame: B = axis box [+-W2,+-H2]; A at rel angle ar = a1-a2.
    float s2, c2; __sincosf(a2, &s2, &c2);
    float sr, cr; __sincosf(a1 - a2, &sr, &cr);

    float dx0 = x1 - x2, dy0 = y1 - y2;
    float cx =  c2 * dx0 + s2 * dy0;
    float cy = -s2 * dx0 + c2 * dy0;

    float W1 = 0.5f * w1, H1 = 0.5f * h1;
    float W2 = 0.5f * w2, H2 = 0.5f * h2;

    float ex = cr * W1, ey = sr * W1;     // A half-edges in B frame (e, f)
    float fx = -sr * H1, fy = cr * H1;

    // A corners, CCW: c+e+f, c-e+f, c-e-f, c+e-f
    float Ax0 = cx + ex + fx, Ay0 = cy + ey + fy;
    float Ax1 = cx - ex + fx, Ay1 = cy - ey + fy;
    float Ax2 = cx - ex - fx, Ay2 = cy - ey - fy;
    float Ax3 = cx + ex - fx, Ay3 = cy + ey - fy;

    // Edge dirs: A0->A1 = -2e, A1->A2 = -2f; opposite edges negated.
    float iEx = __fdividef(-0.5f, ex), iEy = __fdividef(-0.5f, ey);
    float iFx = __fdividef(-0.5f, fx), iFy = __fdividef(-0.5f, fy);

    float area2;
    {   // Edges of A clipped by box B.
        float qEu = fabsf(W2 * iEx), qEv = fabsf(H2 * iEy);   // shared by edges 0,2
        float qFu = fabsf(W2 * iFx), qFv = fabsf(H2 * iFy);   // shared by edges 1,3
        float dt0 = clip_core( Ax0 * iEx, qEu,  Ay0 * iEy, qEv);
        float dt1 = clip_core( Ax1 * iFx, qFu,  Ay1 * iFy, qFv);
        float dt2 = clip_core(-Ax2 * iEx, qEu, -Ay2 * iEy, qEv);
        float dt3 = clip_core(-Ax3 * iFx, qFu, -Ay3 * iFy, qFv);
        // cross(A0,E) = 2W1H1 - 2ce ; cross(A2,-E) = 2W1H1 + 2ce ; likewise F/cf
        float ce = cx * ey - cy * ex;
        float cf = cx * fy - cy * fx;
        area2 = 2.0f * (W1 * H1 * (dt0 + dt1 + dt2 + dt3)
                        + ce * (dt2 - dt0) + cf * (dt3 - dt1));
    }
    {   // Edges of B clipped by box A; every edge contributes dt * 2*W2*H2.
        float a = cr * W2, c = sr * W2;   // A-local images of B's half-axes
        float b = sr * H2, d = cr * H2;
        float cu =  cr * cx + sr * cy;
        float cv = -sr * cx + cr * cy;
        float m = a + b, p = b - a;       // CSE: u0/u2 use m, u1/u3 use p
        float n = d - c, q = c + d;       // v0/v2 use n, v1/v3 use q
        float u0 =  m - cu, v0 =  n - cv; // ( W2,  H2) in A-local
        float u1 =  p - cu, v1 =  q - cv; // (-W2,  H2)
        float u2 = -m - cu, v2 = -n - cv; // (-W2, -H2)
        float u3 = -p - cu, v3 = -q - cv; // ( W2, -H2)
        // dirs: 0->1 = (-2a,2c), 1->2 = (-2b,-2d); 2->3, 3->0 negated
        float ig0x = __fdividef(-0.5f, a), ig0y = __fdividef( 0.5f, c);
        float ig1x = __fdividef(-0.5f, b), ig1y = __fdividef(-0.5f, d);
        float q0u = fabsf(W1 * ig0x), q0v = fabsf(H1 * ig0y);
        float q1u = fabsf(W1 * ig1x), q1v = fabsf(H1 * ig1y);
        float dts = clip_core( u0 * ig0x, q0u,  v0 * ig0y, q0v)
                  + clip_core( u1 * ig1x, q1u,  v1 * ig1y, q1v)
                  + clip_core(-u2 * ig0x, q0u, -v2 * ig0y, q0v)
                  + clip_core(-u3 * ig1x, q1u, -v3 * ig1y, q1v);
        area2 = fmaf(2.0f * W2 * H2, dts, area2);
    }

    float inter2d = 0.5f * fabsf(area2);

    float zmax = fminf(z1 + 0.5f * d1, z2 + 0.5f * d2);
    float zmin = fmaxf(z1 - 0.5f * d1, z2 - 0.5f * d2);
    float inter3d = inter2d * fmaxf(zmax - zmin, 0.0f);

    float v1 = w1 * h1 * d1;
    float v2 = w2 * h2 * d2;
    float iou = __fdividef(inter3d, v1 + v2 - inter3d + 1e-8f);
    return (1.0f - iou) * wgt;
}

__global__ void __launch_bounds__(BLOCK, 14)
iou3d_fused_kernel(const float* __restrict__ pred,
                   const float* __restrict__ target,
                   const float* __restrict__ weight,
                   float* __restrict__ out,
                   int N, float inv_n, int nblocks)
{
    __shared__ float swarp[BLOCK / 32];

    unsigned int t  = blockIdx.x * BLOCK + threadIdx.x;
    unsigned int i0 = 2u * t;
    float loss = 0.0f;

    if (i0 + 1u < (unsigned int)N) {
        // Record pair [i0, i0+1] = 14 floats = 7 float2 per tensor (8B-aligned).
        // Streaming loads: data is read exactly once -> evict-first.
        const float2* p2 = (const float2*)pred   + 7u * t;
        const float2* t2 = (const float2*)target + 7u * t;
        float2 P0 = __ldcs(p2 + 0), P1 = __ldcs(p2 + 1), P2 = __ldcs(p2 + 2),
               P3 = __ldcs(p2 + 3), P4 = __ldcs(p2 + 4), P5 = __ldcs(p2 + 5),
               P6 = __ldcs(p2 + 6);
        float2 T0 = __ldcs(t2 + 0), T1 = __ldcs(t2 + 1), T2 = __ldcs(t2 + 2),
               T3 = __ldcs(t2 + 3), T4 = __ldcs(t2 + 4), T5 = __ldcs(t2 + 5),
               T6 = __ldcs(t2 + 6);
        float2 Wt = __ldcs((const float2*)weight + t);

        loss  = pair_loss(P0.x, P0.y, P1.x, P1.y, P2.x, P2.y, P3.x,
                          T0.x, T0.y, T1.x, T1.y, T2.x, T2.y, T3.x, Wt.x);
        loss += pair_loss(P3.y, P4.x, P4.y, P5.x, P5.y, P6.x, P6.y,
                          T3.y, T4.x, T4.y, T5.x, T5.y, T6.x, T6.y, Wt.y);
    } else if (i0 < (unsigned int)N) {
        // Odd tail element (not taken for N = 2^20; kept for generality)
        const float* b1 = pred   + 7u * i0;
        const float* b2 = target + 7u * i0;
        loss = pair_loss(b1[0], b1[1], b1[2], b1[3], b1[4], b1[5], b1[6],
                         b2[0], b2[1], b2[2], b2[3], b2[4], b2[5], b2[6],
                         weight[i0]);
    }

    // Block reduction: warp shuffle -> shared -> thread 0
    #pragma unroll
    for (int off = 16; off > 0; off >>= 1)
        loss += __shfl_xor_sync(0xffffffffu, loss, off);
    if ((threadIdx.x & 31) == 0) swarp[threadIdx.x >> 5] = loss;
    __syncthreads();

    if (threadIdx.x == 0) {
        float partial = 0.0f;
        #pragma unroll
        for (int w = 0; w < BLOCK / 32; w++) partial += swarp[w];

        unsigned long long v =
            (unsigned long long)((double)partial * FP_SCALE + 0.5) | CNT_ONE;
        unsigned long long old = atomicAdd(&g_acc, v);

        if ((old >> 44) == (unsigned long long)(nblocks - 1)) {
            unsigned long long total = (old & SUM_MASK) + (v & SUM_MASK);
            out[0] = (float)((double)total * (1.0 / FP_SCALE)) * inv_n;
            atomicExch(&g_acc, 0ull);    // reset for next graph replay
        }
    }
}

extern "C" void kernel_launch(void* const* d_in, const int* in_sizes, int n_in,
                              void* d_out, int out_size)
{
    const float* pred   = (const float*)d_in[0];
    const float* target = (const float*)d_in[1];
    const float* weight = (const float*)d_in[2];
    int N = in_sizes[2];

    int grid = (N + 2 * BLOCK - 1) / (2 * BLOCK);   // 4096 for N=1M

    iou3d_fused_kernel<<<grid, BLOCK>>>(pred, target, weight, (float*)d_out,
                                        N, 1.0f / (float)N, grid);
}

// round 11
// speedup vs baseline: 1.0428x; 1.0428x over previous
#include <cuda_runtime.h>

// IoU3DLoss: per-pair rotated 3D IoU -> mean((1-iou)*weight)
// Round 11 = round-9 champion body (abs-form slab clips, corner-cross algebra,
// fast divide, fence-free packed-u64 deterministic reduction) plus:
//  - __launch_bounds__(128, 13): 39-reg target (one-step squeeze, no spill cliff)
//  - 2x / 0.5 scale folding: inter2d = |W1H1*sum(dtA) + ce*(..) + cf*(..) + W2H2*sum(dtB)|
//  - B-corner CSE (m/p/n/q), loss = fma(-iou, w, w)
// NO __ldcs, NO 32-reg cap (round-10 spill regression reverted).

constexpr int BLOCK = 128;
constexpr double FP_SCALE = 8388608.0;            // 2^23
constexpr unsigned long long SUM_MASK = (1ull << 44) - 1ull;
constexpr unsigned long long CNT_ONE  = 1ull << 44;

__device__ unsigned long long g_acc = 0ull;       // reset by last block each launch

// t-interval length inside both slabs, intersected with [0,1].
// pu = u0*idu, qu = |W*idu| (axis-u), likewise v. lo = -p-q, hi = q-p.
__device__ __forceinline__ float clip_core(float pu, float qu, float pv, float qv)
{
    float lo1 = -pu - qu, hi1 = qu - pu;
    float lo2 = -pv - qv, hi2 = qv - pv;
    float tmin = fmaxf(fmaxf(lo1, lo2), 0.0f);
    float tmax = fminf(fminf(hi1, hi2), 1.0f);
    return fmaxf(tmax - tmin, 0.0f);
}

__device__ __forceinline__ float pair_loss(
    float x1, float y1, float z1, float w1, float h1, float d1, float a1,
    float x2, float y2, float z2, float w2, float h2, float d2, float a2,
    float wgt)
{
    // B(target) local frame: B = axis box [+-W2,+-H2]; A at rel angle ar = a1-a2.
    float s2, c2; __sincosf(a2, &s2, &c2);
    float sr, cr; __sincosf(a1 - a2, &sr, &cr);

    float dx0 = x1 - x2, dy0 = y1 - y2;
    float cx =  c2 * dx0 + s2 * dy0;
    float cy = -s2 * dx0 + c2 * dy0;

    float W1 = 0.5f * w1, H1 = 0.5f * h1;
    float W2 = 0.5f * w2, H2 = 0.5f * h2;

    float ex = cr * W1, ey = sr * W1;     // A half-edges in B frame (e, f)
    float fx = -sr * H1, fy = cr * H1;

    // A corners, CCW: c+e+f, c-e+f, c-e-f, c+e-f
    float Ax0 = cx + ex + fx, Ay0 = cy + ey + fy;
    float Ax1 = cx - ex + fx, Ay1 = cy - ey + fy;
    float Ax2 = cx - ex - fx, Ay2 = cy - ey - fy;
    float Ax3 = cx + ex - fx, Ay3 = cy + ey - fy;

    // Edge dirs: A0->A1 = -2e, A1->A2 = -2f; opposite edges negated.
    float iEx = __fdividef(-0.5f, ex), iEy = __fdividef(-0.5f, ey);
    float iFx = __fdividef(-0.5f, fx), iFy = __fdividef(-0.5f, fy);

    float inter2d;
    {   // Edges of A clipped by box B.
        float qEu = fabsf(W2 * iEx), qEv = fabsf(H2 * iEy);   // shared by edges 0,2
        float qFu = fabsf(W2 * iFx), qFv = fabsf(H2 * iFy);   // shared by edges 1,3
        float dt0 = clip_core( Ax0 * iEx, qEu,  Ay0 * iEy, qEv);
        float dt1 = clip_core( Ax1 * iFx, qFu,  Ay1 * iFy, qFv);
        float dt2 = clip_core(-Ax2 * iEx, qEu, -Ay2 * iEy, qEv);
        float dt3 = clip_core(-Ax3 * iFx, qFu, -Ay3 * iFy, qFv);
        // cross(A0,E) = 2W1H1 - 2ce ; cross(A2,-E) = 2W1H1 + 2ce ; likewise F/cf
        float ce = cx * ey - cy * ex;
        float cf = cx * fy - cy * fx;
        float X = W1 * H1 * (dt0 + dt1 + dt2 + dt3)
                + ce * (dt2 - dt0) + cf * (dt3 - dt1);

        // Edges of B clipped by box A; every edge contributes dt * 2*W2*H2.
        float a = cr * W2, c = sr * W2;   // A-local images of B's half-axes
        float b = sr * H2, d = cr * H2;
        float cu =  cr * cx + sr * cy;
        float cv = -sr * cx + cr * cy;
        float m = a + b, p = b - a;       // CSE: u0/u2 use m, u1/u3 use p
        float n = d - c, q = c + d;       // v0/v2 use n, v1/v3 use q
        float u0 =  m - cu, v0 =  n - cv; // ( W2,  H2) in A-local
        float u1 =  p - cu, v1 =  q - cv; // (-W2,  H2)
        float u2 = -m - cu, v2 = -n - cv; // (-W2, -H2)
        float u3 = -p - cu, v3 = -q - cv; // ( W2, -H2)
        // dirs: 0->1 = (-2a,2c), 1->2 = (-2b,-2d); 2->3, 3->0 negated
        float ig0x = __fdividef(-0.5f, a), ig0y = __fdividef( 0.5f, c);
        float ig1x = __fdividef(-0.5f, b), ig1y = __fdividef(-0.5f, d);
        float q0u = fabsf(W1 * ig0x), q0v = fabsf(H1 * ig0y);
        float q1u = fabsf(W1 * ig1x), q1v = fabsf(H1 * ig1y);
        float dts = clip_core( u0 * ig0x, q0u,  v0 * ig0y, q0v)
                  + clip_core( u1 * ig1x, q1u,  v1 * ig1y, q1v)
                  + clip_core(-u2 * ig0x, q0u, -v2 * ig0y, q0v)
                  + clip_core(-u3 * ig1x, q1u, -v3 * ig1y, q1v);

        // 2x from both groups cancels the 0.5 shoelace factor:
        inter2d = fabsf(fmaf(W2 * H2, dts, X));
    }

    float zmax = fminf(z1 + 0.5f * d1, z2 + 0.5f * d2);
    float zmin = fmaxf(z1 - 0.5f * d1, z2 - 0.5f * d2);
    float inter3d = inter2d * fmaxf(zmax - zmin, 0.0f);

    float v1 = w1 * h1 * d1;
    float v2 = w2 * h2 * d2;
    float iou = __fdividef(inter3d, v1 + v2 - inter3d + 1e-8f);
    return fmaf(-iou, wgt, wgt);
}

__global__ void __launch_bounds__(BLOCK, 13)
iou3d_fused_kernel(const float* __restrict__ pred,
                   const float* __restrict__ target,
                   const float* __restrict__ weight,
                   float* __restrict__ out,
                   int N, float inv_n, int nblocks)
{
    __shared__ float swarp[BLOCK / 32];

    unsigned int t  = blockIdx.x * BLOCK + threadIdx.x;
    unsigned int i0 = 2u * t;
    float loss = 0.0f;

    if (i0 + 1u < (unsigned int)N) {
        // Record pair [i0, i0+1] = 14 floats = 7 float2 per tensor (8B-aligned)
        const float2* p2 = (const float2*)pred   + 7u * t;
        const float2* t2 = (const float2*)target + 7u * t;
        float2 P0 = p2[0], P1 = p2[1], P2 = p2[2], P3 = p2[3], P4 = p2[4], P5 = p2[5], P6 = p2[6];
        float2 T0 = t2[0], T1 = t2[1], T2 = t2[2], T3 = t2[3], T4 = t2[4], T5 = t2[5], T6 = t2[6];
        float2 Wt = ((const float2*)weight)[t];

        loss  = pair_loss(P0.x, P0.y, P1.x, P1.y, P2.x, P2.y, P3.x,
                          T0.x, T0.y, T1.x, T1.y, T2.x, T2.y, T3.x, Wt.x);
        loss += pair_loss(P3.y, P4.x, P4.y, P5.x, P5.y, P6.x, P6.y,
                          T3.y, T4.x, T4.y, T5.x, T5.y, T6.x, T6.y, Wt.y);
    } else if (i0 < (unsigned int)N) {
        // Odd tail element (not taken for N = 2^20; kept for generality)
        const float* b1 = pred   + 7u * i0;
        const float* b2 = target + 7u * i0;
        loss = pair_loss(b1[0], b1[1], b1[2], b1[3], b1[4], b1[5], b1[6],
                         b2[0], b2[1], b2[2], b2[3], b2[4], b2[5], b2[6],
                         weight[i0]);
    }

    // Block reduction: warp shuffle -> shared -> thread 0
    #pragma unroll
    for (int off = 16; off > 0; off >>= 1)
        loss += __shfl_xor_sync(0xffffffffu, loss, off);
    if ((threadIdx.x & 31) == 0) swarp[threadIdx.x >> 5] = loss;
    __syncthreads();

    if (threadIdx.x == 0) {
        float partial = 0.0f;
        #pragma unroll
        for (int w = 0; w < BLOCK / 32; w++) partial += swarp[w];

        unsigned long long v =
            (unsigned long long)((double)partial * FP_SCALE + 0.5) | CNT_ONE;
        unsigned long long old = atomicAdd(&g_acc, v);

        if ((old >> 44) == (unsigned long long)(nblocks - 1)) {
            unsigned long long total = (old & SUM_MASK) + (v & SUM_MASK);
            out[0] = (float)((double)total * (1.0 / FP_SCALE)) * inv_n;
            atomicExch(&g_acc, 0ull);    // reset for next graph replay
        }
    }
}

extern "C" void kernel_launch(void* const* d_in, const int* in_sizes, int n_in,
                              void* d_out, int out_size)
{
    const float* pred   = (const float*)d_in[0];
    const float* target = (const float*)d_in[1];
    const float* weight = (const float*)d_in[2];
    int N = in_sizes[2];

    int grid = (N + 2 * BLOCK - 1) / (2 * BLOCK);   // 4096 for N=1M

    iou3d_fused_kernel<<<grid, BLOCK>>>(pred, target, weight, (float*)d_out,
                                        N, 1.0f / (float)N, grid);
}

// round 14
// speedup vs baseline: 1.1552x; 1.1078x over previous
#include <cuda_runtime.h>

// IoU3DLoss: per-pair rotated 3D IoU -> mean((1-iou)*weight)
// Round 13 = round-12 (fixed compile: volume vars renamed vol1/vol2, which had
// collided with B-corner locals v0..v3 after brace-flattening).
// Structure: EXACT round-9 champion (regs=40, 12 blocks/SM, no occupancy forcing)
// + zero-pressure algebraic folds:
//  - scale folding: inter2d = |W1H1*sum(dtA) + ce(dt2-dt0) + cf(dt3-dt1) + W2H2*sum(dtB)|
//  - B-corner CSE (m/p/n/q)
//  - loss = fma(-iou, w, w)
// Fence-free packed-u64 deterministic reduction (sum fixed-point | block counter).

constexpr int BLOCK = 128;
constexpr double FP_SCALE = 8388608.0;            // 2^23
constexpr unsigned long long SUM_MASK = (1ull << 44) - 1ull;
constexpr unsigned long long CNT_ONE  = 1ull << 44;

__device__ unsigned long long g_acc = 0ull;       // reset by last block each launch

// t-interval length inside both slabs, intersected with [0,1].
// pu = u0*idu, qu = |W*idu| (axis-u), likewise v. lo = -p-q, hi = q-p.
__device__ __forceinline__ float clip_core(float pu, float qu, float pv, float qv)
{
    float lo1 = -pu - qu, hi1 = qu - pu;
    float lo2 = -pv - qv, hi2 = qv - pv;
    float tmin = fmaxf(fmaxf(lo1, lo2), 0.0f);
    float tmax = fminf(fminf(hi1, hi2), 1.0f);
    return fmaxf(tmax - tmin, 0.0f);
}

__device__ __forceinline__ float pair_loss(
    float x1, float y1, float z1, float w1, float h1, float d1, float a1,
    float x2, float y2, float z2, float w2, float h2, float d2, float a2,
    float wgt)
{
    // B(target) local frame: B = axis box [+-W2,+-H2]; A at rel angle ar = a1-a2.
    float s2, c2; __sincosf(a2, &s2, &c2);
    float sr, cr; __sincosf(a1 - a2, &sr, &cr);

    float dx0 = x1 - x2, dy0 = y1 - y2;
    float cx =  c2 * dx0 + s2 * dy0;
    float cy = -s2 * dx0 + c2 * dy0;

    float W1 = 0.5f * w1, H1 = 0.5f * h1;
    float W2 = 0.5f * w2, H2 = 0.5f * h2;

    float ex = cr * W1, ey = sr * W1;     // A half-edges in B frame (e, f)
    float fx = -sr * H1, fy = cr * H1;

    // A corners, CCW: c+e+f, c-e+f, c-e-f, c+e-f
    float Ax0 = cx + ex + fx, Ay0 = cy + ey + fy;
    float Ax1 = cx - ex + fx, Ay1 = cy - ey + fy;
    float Ax2 = cx - ex - fx, Ay2 = cy - ey - fy;
    float Ax3 = cx + ex - fx, Ay3 = cy + ey - fy;

    // Edge dirs: A0->A1 = -2e, A1->A2 = -2f; opposite edges negated.
    float iEx = __fdividef(-0.5f, ex), iEy = __fdividef(-0.5f, ey);
    float iFx = __fdividef(-0.5f, fx), iFy = __fdividef(-0.5f, fy);

    // Edges of A clipped by box B.
    float qEu = fabsf(W2 * iEx), qEv = fabsf(H2 * iEy);   // shared by edges 0,2
    float qFu = fabsf(W2 * iFx), qFv = fabsf(H2 * iFy);   // shared by edges 1,3
    float dt0 = clip_core( Ax0 * iEx, qEu,  Ay0 * iEy, qEv);
    float dt1 = clip_core( Ax1 * iFx, qFu,  Ay1 * iFy, qFv);
    float dt2 = clip_core(-Ax2 * iEx, qEu, -Ay2 * iEy, qEv);
    float dt3 = clip_core(-Ax3 * iFx, qFu, -Ay3 * iFy, qFv);
    // cross(A0,E) = 2W1H1 - 2ce ; cross(A2,-E) = 2W1H1 + 2ce ; likewise F/cf
    float ce = cx * ey - cy * ex;
    float cf = cx * fy - cy * fx;
    float X = W1 * H1 * (dt0 + dt1 + dt2 + dt3)
            + ce * (dt2 - dt0) + cf * (dt3 - dt1);

    // Edges of B clipped by box A; every edge contributes dt * 2*W2*H2.
    float a = cr * W2, c = sr * W2;   // A-local images of B's half-axes
    float b = sr * H2, d = cr * H2;
    float cu =  cr * cx + sr * cy;
    float cv = -sr * cx + cr * cy;
    float m = a + b, p = b - a;       // CSE: corners share these sums
    float n = d - c, q = c + d;
    float u0 =  m - cu, v0 =  n - cv; // ( W2,  H2) in A-local
    float u1 =  p - cu, v1 =  q - cv; // (-W2,  H2)
    float u2 = -m - cu, v2 = -n - cv; // (-W2, -H2)
    float u3 = -p - cu, v3 = -q - cv; // ( W2, -H2)
    // dirs: 0->1 = (-2a,2c), 1->2 = (-2b,-2d); 2->3, 3->0 negated
    float ig0x = __fdividef(-0.5f, a), ig0y = __fdividef( 0.5f, c);
    float ig1x = __fdividef(-0.5f, b), ig1y = __fdividef(-0.5f, d);
    float q0u = fabsf(W1 * ig0x), q0v = fabsf(H1 * ig0y);
    float q1u = fabsf(W1 * ig1x), q1v = fabsf(H1 * ig1y);
    float dts = clip_core( u0 * ig0x, q0u,  v0 * ig0y, q0v)
              + clip_core( u1 * ig1x, q1u,  v1 * ig1y, q1v)
              + clip_core(-u2 * ig0x, q0u, -v2 * ig0y, q0v)
              + clip_core(-u3 * ig1x, q1u, -v3 * ig1y, q1v);

    // 2x from both groups cancels the 0.5 shoelace factor:
    float inter2d = fabsf(fmaf(W2 * H2, dts, X));

    float zmax = fminf(z1 + 0.5f * d1, z2 + 0.5f * d2);
    float zmin = fmaxf(z1 - 0.5f * d1, z2 - 0.5f * d2);
    float inter3d = inter2d * fmaxf(zmax - zmin, 0.0f);

    float vol1 = w1 * h1 * d1;
    float vol2 = w2 * h2 * d2;
    float iou = __fdividef(inter3d, vol1 + vol2 - inter3d + 1e-8f);
    return fmaf(-iou, wgt, wgt);
}

__global__ void __launch_bounds__(BLOCK)
iou3d_fused_kernel(const float* __restrict__ pred,
                   const float* __restrict__ target,
                   const float* __restrict__ weight,
                   float* __restrict__ out,
                   int N, float inv_n, int nblocks)
{
    __shared__ float swarp[BLOCK / 32];

    unsigned int t  = blockIdx.x * BLOCK + threadIdx.x;
    unsigned int i0 = 2u * t;
    float loss = 0.0f;

    if (i0 + 1u < (unsigned int)N) {
        // Record pair [i0, i0+1] = 14 floats = 7 float2 per tensor (8B-aligned)
        const float2* p2 = (const float2*)pred   + 7u * t;
        const float2* t2 = (const float2*)target + 7u * t;
        float2 P0 = p2[0], P1 = p2[1], P2 = p2[2], P3 = p2[3], P4 = p2[4], P5 = p2[5], P6 = p2[6];
        float2 T0 = t2[0], T1 = t2[1], T2 = t2[2], T3 = t2[3], T4 = t2[4], T5 = t2[5], T6 = t2[6];
        float2 Wt = ((const float2*)weight)[t];

        loss  = pair_loss(P0.x, P0.y, P1.x, P1.y, P2.x, P2.y, P3.x,
                          T0.x, T0.y, T1.x, T1.y, T2.x, T2.y, T3.x, Wt.x);
        loss += pair_loss(P3.y, P4.x, P4.y, P5.x, P5.y, P6.x, P6.y,
                          T3.y, T4.x, T4.y, T5.x, T5.y, T6.x, T6.y, Wt.y);
    } else if (i0 < (unsigned int)N) {
        // Odd tail element (not taken for N = 2^20; kept for generality)
        const float* b1 = pred   + 7u * i0;
        const float* b2 = target + 7u * i0;
        loss = pair_loss(b1[0], b1[1], b1[2], b1[3], b1[4], b1[5], b1[6],
                         b2[0], b2[1], b2[2], b2[3], b2[4], b2[5], b2[6],
                         weight[i0]);
    }

    // Block reduction: warp shuffle -> shared -> thread 0
    #pragma unroll
    for (int off = 16; off > 0; off >>= 1)
        loss += __shfl_xor_sync(0xffffffffu, loss, off);
    if ((threadIdx.x & 31) == 0) swarp[threadIdx.x >> 5] = loss;
    __syncthreads();

    if (threadIdx.x == 0) {
        float partial = 0.0f;
        #pragma unroll
        for (int w = 0; w < BLOCK / 32; w++) partial += swarp[w];

        unsigned long long v =
            (unsigned long long)((double)partial * FP_SCALE + 0.5) | CNT_ONE;
        unsigned long long old = atomicAdd(&g_acc, v);

        if ((old >> 44) == (unsigned long long)(nblocks - 1)) {
            unsigned long long total = (old & SUM_MASK) + (v & SUM_MASK);
            out[0] = (float)((double)total * (1.0 / FP_SCALE)) * inv_n;
            atomicExch(&g_acc, 0ull);    // reset for next graph replay
        }
    }
}

extern "C" void kernel_launch(void* const* d_in, const int* in_sizes, int n_in,
                              void* d_out, int out_size)
{
    const float* pred   = (const float*)d_in[0];
    const float* target = (const float*)d_in[1];
    const float* weight = (const float*)d_in[2];
    int N = in_sizes[2];

    int grid = (N + 2 * BLOCK - 1) / (2 * BLOCK);   // 4096 for N=1M

    iou3d_fused_kernel<<<grid, BLOCK>>>(pred, target, weight, (float*)d_out,
                                        N, 1.0f / (float)N, grid);
}